// round 3
// baseline (speedup 1.0000x reference)
#include <cuda_runtime.h>
#include <cstdint>

#define BA (128 * 8732)       // 1117696 anchors, == 4366 * 256 exactly
#define NC 21
#define NBF 262144            // fine bins: bits >> 13 (covers all nonneg floats)
#define NBC 4096              // coarse bins: fine >> 6
#define NBLK 4366             // BA / 256

// ---- scratch (no cudaMalloc allowed) ----
__device__ unsigned g_fcnt[NBF];
__device__ float    g_fsum[NBF];
__device__ unsigned g_ccnt[NBC];
__device__ float    g_csum[NBC];
__device__ unsigned g_np;
__device__ float    g_posce, g_locsum;

// ---------------------------------------------------------------------------
__global__ void k_init() {
    int tid = blockIdx.x * blockDim.x + threadIdx.x;   // 1024 blk * 256 = 262144
    g_fcnt[tid] = 0u;
    g_fsum[tid] = 0.f;
    if (tid == 0) { g_np = 0u; g_posce = 0.f; g_locsum = 0.f; }
}

// ---------------------------------------------------------------------------
// Main pass: coalesced clf staging -> CE -> pos accum + fine histogram REDs
__global__ void __launch_bounds__(256) k_main(
    const float* __restrict__ ploc, const float* __restrict__ pclf,
    const float* __restrict__ tloc, const int* __restrict__ tcls)
{
    __shared__ float s_row[256 * NC];       // 21504 B
    __shared__ float s_posce, s_loc;
    __shared__ unsigned s_np;

    int tid = threadIdx.x;
    if (tid == 0) { s_posce = 0.f; s_loc = 0.f; s_np = 0u; }

    // Coalesced float4 stage: 256*21*4 = 21504 B = 1344 float4, 16B-divisible.
    {
        const float4* src = reinterpret_cast<const float4*>(
            pclf + (size_t)blockIdx.x * (256 * NC));
        float4* dst = reinterpret_cast<float4*>(s_row);
#pragma unroll
        for (int i = 0; i < 6; i++) {
            int j = i * 256 + tid;
            if (j < 1344) dst[j] = src[j];
        }
    }
    __syncthreads();

    int idx = blockIdx.x * 256 + tid;       // always valid: BA % 256 == 0
    int tc = tcls[idx];

    const float* row = s_row + tid * NC;    // 21 coprime 32 -> conflict-free LDS
    float m = -1e30f, xt = 0.f;
    float v[NC];
#pragma unroll
    for (int c = 0; c < NC; c++) {
        float val = row[c];
        v[c] = val;
        m = fmaxf(m, val);
        xt = (c == tc) ? val : xt;          // predicated select, no spill
    }
    float s = 0.f;
#pragma unroll
    for (int c = 0; c < NC; c++) s += __expf(v[c] - m);
    float ce = __logf(s) + m - xt;

    unsigned bin = 0xFFFFFFFFu;             // sentinel for positives
    float ce_neg = 0.f;
    if (tc != 0) {
        atomicAdd(&s_posce, ce);
        atomicAdd(&s_np, 1u);
        float4 p = *reinterpret_cast<const float4*>(ploc + (size_t)idx * 4);
        float4 t = *reinterpret_cast<const float4*>(tloc + (size_t)idx * 4);
        atomicAdd(&s_loc, fabsf(p.x - t.x) + fabsf(p.y - t.y) +
                          fabsf(p.z - t.z) + fabsf(p.w - t.w));
    } else {
        ce_neg = fmaxf(ce, 0.f);
        bin = __float_as_uint(ce_neg) >> 13;
    }

    // Warp-aggregated count REDs; per-lane sum REDs (no return -> REDG).
    unsigned mask = __match_any_sync(0xFFFFFFFFu, bin);
    if (bin != 0xFFFFFFFFu) {
        atomicAdd(&g_fsum[bin], ce_neg);
        if ((unsigned)(__ffs(mask) - 1) == (threadIdx.x & 31u))
            atomicAdd(&g_fcnt[bin], (unsigned)__popc(mask));
    }

    __syncthreads();
    if (tid == 0) {
        if (s_np) atomicAdd(&g_np, s_np);
        atomicAdd(&g_posce, s_posce);
        atomicAdd(&g_locsum, s_loc);
    }
}

// ---------------------------------------------------------------------------
// Fine -> coarse (64:1). 32 blocks x 128 threads = 4096, 1 coarse bin each.
__global__ void __launch_bounds__(128) k_reduce() {
    int cb = blockIdx.x * 128 + threadIdx.x;
    int base = cb << 6;
    unsigned c = 0u; float s = 0.f;
#pragma unroll 8
    for (int i = 0; i < 64; i++) { c += g_fcnt[base + i]; s += g_fsum[base + i]; }
    g_ccnt[cb] = c;
    g_csum[cb] = s;
}

// ---------------------------------------------------------------------------
// Final: select threshold coarse bin, refine on its 64 fine bins, emit losses.
__global__ void __launch_bounds__(256) k_final(float* __restrict__ out) {
    __shared__ unsigned s_sf[256];
    __shared__ float    s_red[256];
    __shared__ int      s_bin;
    __shared__ unsigned s_r;
    __shared__ unsigned s_fc[64];
    __shared__ float    s_fs[64];
    __shared__ float    s_top;

    int tid = threadIdx.x;
    unsigned np = g_np;
    unsigned nn = (unsigned)BA - np;
    unsigned k = (np == 0u) ? 0u : min(3u * np, nn);

    float top = 0.f;
    if (k > 0u) {
        // ---- coarse suffix-select: find t1 with cnt_gt(t1) < k <= cnt_ge(t1)
        const int per = NBC / 256;   // 16
        int base = tid * per;
        unsigned local = 0u;
        float    lsum  = 0.f;
#pragma unroll
        for (int i = 0; i < per; i++) { local += g_ccnt[base + i]; }
        s_sf[tid] = local;
        __syncthreads();
        for (int off = 1; off < 256; off <<= 1) {
            unsigned vv = (tid + off < 256) ? s_sf[tid + off] : 0u;
            __syncthreads();
            s_sf[tid] += vv;
            __syncthreads();
        }
        unsigned running = (tid < 255) ? s_sf[tid + 1] : 0u;
        for (int i = per - 1; i >= 0; i--) {
            unsigned c = g_ccnt[base + i];
            if (c > 0u && running < k && running + c >= k) {
                s_bin = base + i; s_r = k - running;
            }
            running += c;
        }
        __syncthreads();
        int t1 = s_bin; unsigned r = s_r;

        // ---- exact sum of coarse bins strictly above t1
#pragma unroll
        for (int i = 0; i < per; i++) {
            int b = base + i;
            if (b > t1) lsum += g_csum[b];
        }
        s_red[tid] = lsum;
        __syncthreads();
        for (int off = 128; off >= 1; off >>= 1) {
            if (tid < off) s_red[tid] += s_red[tid + off];
            __syncthreads();
        }
        float above = s_red[0];

        // ---- refine within coarse bin t1 over its 64 fine bins
        if (tid < 64) {
            int fb = (t1 << 6) + tid;
            s_fc[tid] = g_fcnt[fb];
            s_fs[tid] = g_fsum[fb];
        }
        __syncthreads();
        if (tid == 0) {
            unsigned run = 0u;
            float acc = above;
            for (int i = 63; i >= 0; i--) {
                unsigned c = s_fc[i];
                if (c > 0u) {
                    if (run + c >= r) {
                        unsigned r2 = r - run;                    // top-r2 of boundary bin
                        acc += (float)r2 * (s_fs[i] / (float)c);  // bin-mean approx (2^-10 rel width)
                        break;
                    }
                    acc += s_fs[i];
                    run += c;
                }
            }
            s_top = acc;
        }
        __syncthreads();
        top = s_top;
    }

    if (tid == 0) {
        float fnp = (float)np, fk = (float)k;
        out[0] = (g_posce + top) / (fnp + fk);   // loss_cls
        out[1] = g_locsum / fnp;                 // loss_loc
    }
}

// ---------------------------------------------------------------------------
extern "C" void kernel_launch(void* const* d_in, const int* in_sizes, int n_in,
                              void* d_out, int out_size)
{
    const float* ploc = (const float*)d_in[0];
    const float* pclf = (const float*)d_in[1];
    const float* tloc = (const float*)d_in[2];
    const int*   tcls = (const int*)d_in[3];
    float* out = (float*)d_out;

    k_init<<<NBF / 256, 256>>>();
    k_main<<<NBLK, 256>>>(ploc, pclf, tloc, tcls);
    k_reduce<<<NBC / 128, 128>>>();
    k_final<<<1, 256>>>(out);
}

// round 4
// speedup vs baseline: 1.1987x; 1.1987x over previous
#include <cuda_runtime.h>
#include <cstdint>

#define BA (128 * 8732)       // 1117696 anchors == 1091 * 1024
#define NC 21
#define NBF 262144            // fine bins: float bits >> 13
#define NBC 4096              // coarse bins: fine >> 6
#define NBLK 1091             // BA / 1024
#define HSZ 2048              // smem hash slots (>= 1024 inserts, load <= 0.5)
#define EMPTY 0xFFFFFFFFu

// ---- scratch (no cudaMalloc allowed) ----
__device__ unsigned g_fcnt[NBF];
__device__ float    g_fsum[NBF];
__device__ unsigned g_ccnt[NBC];
__device__ float    g_csum[NBC];
__device__ unsigned g_np;
__device__ float    g_posce, g_locsum;

// ---------------------------------------------------------------------------
__global__ void k_init() {   // 256 blocks x 256 threads, uint4/float4 stores
    int tid = blockIdx.x * blockDim.x + threadIdx.x;   // 65536
    reinterpret_cast<uint4*>(g_fcnt)[tid] = make_uint4(0u, 0u, 0u, 0u);
    reinterpret_cast<float4*>(g_fsum)[tid] = make_float4(0.f, 0.f, 0.f, 0.f);
    if (tid == 0) { g_np = 0u; g_posce = 0.f; g_locsum = 0.f; }
}

// ---------------------------------------------------------------------------
// Main pass: staged clf -> CE -> pos accum; negatives into smem hash histogram
__global__ void __launch_bounds__(256) k_main(
    const float* __restrict__ ploc, const float* __restrict__ pclf,
    const float* __restrict__ tloc, const int* __restrict__ tcls)
{
    __shared__ float    s_row[256 * NC];     // 21504 B staging
    __shared__ unsigned s_key[HSZ];          // 8 KB
    __shared__ unsigned s_hc[HSZ];           // 8 KB
    __shared__ float    s_hs[HSZ];           // 8 KB
    __shared__ float    s_posce, s_loc;
    __shared__ unsigned s_np;

    int tid = threadIdx.x;
#pragma unroll
    for (int i = 0; i < HSZ / 256; i++) {
        int j = i * 256 + tid;
        s_key[j] = EMPTY; s_hc[j] = 0u; s_hs[j] = 0.f;
    }
    if (tid == 0) { s_posce = 0.f; s_loc = 0.f; s_np = 0u; }
    __syncthreads();

#pragma unroll 1
    for (int it = 0; it < 4; it++) {
        int chunk = blockIdx.x * 1024 + it * 256;      // anchor base of this chunk
        // coalesced float4 stage: 256*21 floats = 1344 float4
        {
            const float4* src = reinterpret_cast<const float4*>(
                pclf + (size_t)chunk * NC);
            float4* dst = reinterpret_cast<float4*>(s_row);
#pragma unroll
            for (int i = 0; i < 6; i++) {
                int j = i * 256 + tid;
                if (j < 1344) dst[j] = src[j];
            }
        }
        __syncthreads();

        int idx = chunk + tid;
        int tc = tcls[idx];
        const float* row = s_row + tid * NC;           // 21 coprime 32: no conflicts
        float m = -1e30f, xt = 0.f;
        float v[NC];
#pragma unroll
        for (int c = 0; c < NC; c++) {
            float val = row[c];
            v[c] = val;
            m = fmaxf(m, val);
            xt = (c == tc) ? val : xt;
        }
        float s = 0.f;
#pragma unroll
        for (int c = 0; c < NC; c++) s += __expf(v[c] - m);
        float ce = __logf(s) + m - xt;

        if (tc != 0) {
            atomicAdd(&s_posce, ce);
            atomicAdd(&s_np, 1u);
            float4 p = *reinterpret_cast<const float4*>(ploc + (size_t)idx * 4);
            float4 t = *reinterpret_cast<const float4*>(tloc + (size_t)idx * 4);
            atomicAdd(&s_loc, fabsf(p.x - t.x) + fabsf(p.y - t.y) +
                              fabsf(p.z - t.z) + fabsf(p.w - t.w));
        } else {
            unsigned bin = __float_as_uint(ce) >> 13;  // CE >= 0 always
            unsigned h = (bin * 2654435761u) >> 21;    // 11-bit hash
            for (;;) {
                unsigned old = atomicCAS(&s_key[h], EMPTY, bin);
                if (old == EMPTY || old == bin) {
                    atomicAdd(&s_hc[h], 1u);
                    atomicAdd(&s_hs[h], ce);
                    break;
                }
                h = (h + 1) & (HSZ - 1);
            }
        }
        __syncthreads();   // protect s_row before next stage
    }

    // flush hash (one RED pair per occupied slot -> <=1091 REDs per global bin)
#pragma unroll
    for (int i = 0; i < HSZ / 256; i++) {
        int j = i * 256 + tid;
        unsigned key = s_key[j];
        if (key != EMPTY) {
            atomicAdd(&g_fcnt[key], s_hc[j]);
            atomicAdd(&g_fsum[key], s_hs[j]);
        }
    }
    if (tid == 0) {
        if (s_np) atomicAdd(&g_np, s_np);
        atomicAdd(&g_posce, s_posce);
        atomicAdd(&g_locsum, s_loc);
    }
}

// ---------------------------------------------------------------------------
// Fine -> coarse (64:1). 32 blocks x 128 threads.
__global__ void __launch_bounds__(128) k_reduce() {
    int cb = blockIdx.x * 128 + threadIdx.x;
    int base = cb << 6;
    unsigned c = 0u; float s = 0.f;
#pragma unroll 8
    for (int i = 0; i < 64; i++) { c += g_fcnt[base + i]; s += g_fsum[base + i]; }
    g_ccnt[cb] = c;
    g_csum[cb] = s;
}

// ---------------------------------------------------------------------------
// Final: 1 block x 1024 threads. Smem-staged coarse hist, shuffle scan,
// refine threshold bin over its 64 fine bins, emit losses.
__global__ void __launch_bounds__(1024) k_final(float* __restrict__ out) {
    __shared__ unsigned sW[NBC];     // 16 KB
    __shared__ float    sS[NBC];     // 16 KB
    __shared__ unsigned s_wt[32];
    __shared__ float    s_rd[32];
    __shared__ int      s_t1;
    __shared__ unsigned s_fc[64];
    __shared__ float    s_fs[64];

    int tid  = threadIdx.x;
    int lane = tid & 31, wrp = tid >> 5;

#pragma unroll
    for (int i = 0; i < 4; i++) {
        int b = i * 1024 + tid;
        sW[b] = g_ccnt[b];
        sS[b] = g_csum[b];
    }
    if (tid == 0) s_t1 = -1;
    __syncthreads();

    unsigned np = g_np;
    unsigned nn = (unsigned)BA - np;
    unsigned k  = (np == 0u) ? 0u : min(3u * np, nn);

    float top = 0.f;
    if (k > 0u) {
        // thread owns bins [4t, 4t+4)
        int b0 = tid * 4;
        unsigned w0 = sW[b0], w1 = sW[b0 + 1], w2 = sW[b0 + 2], w3 = sW[b0 + 3];
        unsigned T = w0 + w1 + w2 + w3;

        // warp inclusive scan of T
        unsigned inc = T;
#pragma unroll
        for (int off = 1; off < 32; off <<= 1) {
            unsigned u = __shfl_up_sync(0xFFFFFFFFu, inc, off);
            if (lane >= off) inc += u;
        }
        if (lane == 31) s_wt[wrp] = inc;
        __syncthreads();
        if (wrp == 0) {
            unsigned wv = s_wt[lane];
            unsigned wi = wv;
#pragma unroll
            for (int off = 1; off < 32; off <<= 1) {
                unsigned u = __shfl_up_sync(0xFFFFFFFFu, wi, off);
                if (lane >= off) wi += u;
            }
            s_wt[lane] = wi - wv;        // exclusive warp offsets
        }
        __syncthreads();
        unsigned TOT  = s_wt[31] + __shfl_sync(0xFFFFFFFFu, 0u, 0); // placeholder
        // recompute TOT robustly: last warp's offset + its inclusive total
        // (TOT = total negatives; use nn-equivalent from scan)
        // exclusive prefix for this thread's first bin:
        unsigned texc = s_wt[wrp] + inc - T;
        // grand total:
        __shared__ unsigned s_tot;
        if (tid == 1023) s_tot = texc + T;
        __syncthreads();
        TOT = s_tot;

        // find t1 = max bin with P_excl(bin) <= TOT - k
        unsigned lim = TOT - k;
        unsigned p = texc;
        int cand = -1;
        if (p <= lim) cand = b0;
        p += w0; if (p <= lim) cand = b0 + 1;
        p += w1; if (p <= lim) cand = b0 + 2;
        p += w2; if (p <= lim) cand = b0 + 3;
        if (cand >= 0) atomicMax(&s_t1, cand);
        __syncthreads();
        int t1 = s_t1;

        // r = k - cnt_gt(t1);  cnt_gt = TOT - P_incl(t1)
        unsigned pincl_t1 = 0u;
        if (t1 >= b0 && t1 < b0 + 4) {
            unsigned q = texc;
            if (t1 >= b0)     q += w0;
            if (t1 >= b0 + 1) q += w1;
            if (t1 >= b0 + 2) q += w2;
            if (t1 >= b0 + 3) q += w3;
            pincl_t1 = q;
        }
        // broadcast pincl via reduction (only owner nonzero)
        __shared__ unsigned s_pin;
        if (tid == 0) s_pin = 0u;
        __syncthreads();
        if (pincl_t1) atomicMax(&s_pin, pincl_t1);
        __syncthreads();
        unsigned r = k - (TOT - s_pin);

        // exact sum of coarse bins strictly above t1
        float ls = 0.f;
#pragma unroll
        for (int i = 0; i < 4; i++) {
            int b = b0 + i;
            if (b > t1) ls += sS[b];
        }
#pragma unroll
        for (int off = 16; off >= 1; off >>= 1)
            ls += __shfl_down_sync(0xFFFFFFFFu, ls, off);
        if (lane == 0) s_rd[wrp] = ls;
        __syncthreads();
        if (wrp == 0) {
            float vsum = s_rd[lane];
#pragma unroll
            for (int off = 16; off >= 1; off >>= 1)
                vsum += __shfl_down_sync(0xFFFFFFFFu, vsum, off);
            if (lane == 0) s_rd[0] = vsum;
        }
        // load the 64 fine bins of t1
        if (tid < 64) {
            int fb = (t1 << 6) + tid;
            s_fc[tid] = g_fcnt[fb];
            s_fs[tid] = g_fsum[fb];
        }
        __syncthreads();
        if (tid == 0) {
            unsigned run = 0u;
            float acc = s_rd[0];
            for (int i = 63; i >= 0; i--) {
                unsigned c = s_fc[i];
                if (c > 0u) {
                    if (run + c >= r) {
                        unsigned r2 = r - run;
                        acc += (float)r2 * (s_fs[i] / (float)c);  // 2^-10 bin width
                        break;
                    }
                    acc += s_fs[i];
                    run += c;
                }
            }
            s_rd[1] = acc;
        }
        __syncthreads();
        top = s_rd[1];
    }

    if (tid == 0) {
        float fnp = (float)np, fk = (float)k;
        out[0] = (g_posce + top) / (fnp + fk);   // loss_cls
        out[1] = g_locsum / fnp;                 // loss_loc
    }
}

// ---------------------------------------------------------------------------
extern "C" void kernel_launch(void* const* d_in, const int* in_sizes, int n_in,
                              void* d_out, int out_size)
{
    const float* ploc = (const float*)d_in[0];
    const float* pclf = (const float*)d_in[1];
    const float* tloc = (const float*)d_in[2];
    const int*   tcls = (const int*)d_in[3];
    float* out = (float*)d_out;

    k_init<<<256, 256>>>();
    k_main<<<NBLK, 256>>>(ploc, pclf, tloc, tcls);
    k_reduce<<<NBC / 128, 128>>>();
    k_final<<<1, 1024>>>(out);
}

// round 6
// speedup vs baseline: 1.8735x; 1.5630x over previous
#include <cuda_runtime.h>
#include <cstdint>

#define BA (128 * 8732)     // 1117696 anchors; BA/256 == 4366 exactly
#define NC 21
#define NBLK_MAIN 4366
#define NB1 2048            // coarse bins: bits >> 21 (CE >= 0 -> bin <= 1020)
#define SUB 256             // sub-bins within boundary coarse bin: (bits>>13)&0xFF
#define NF4 (BA / 4)        // 279424 float4
#define NBLK_REF 1092       // ceil(NF4/256)

// ---- scratch (no cudaMalloc allowed) ----
__device__ float    g_ce[BA];
__device__ unsigned g_h1c[NB1];
__device__ float    g_h1s[NB1];
__device__ unsigned g_rc[SUB];
__device__ float    g_rs[SUB];
__device__ unsigned g_np;
__device__ float    g_posce, g_locsum;
__device__ int      g_t1;
__device__ unsigned g_r, g_k;
__device__ float    g_above;

// ---------------------------------------------------------------------------
__global__ void k_init() {
    int tid = blockIdx.x * 1024 + threadIdx.x;   // 2 blocks x 1024 = 2048
    g_h1c[tid] = 0u; g_h1s[tid] = 0.f;
    if (tid < SUB) { g_rc[tid] = 0u; g_rs[tid] = 0.f; }
    if (tid == 0) { g_np = 0u; g_posce = 0.f; g_locsum = 0.f; }
}

// ---------------------------------------------------------------------------
// Main pass: coalesced clf staging -> CE -> pos accum + direct smem coarse hist
__global__ void __launch_bounds__(256) k_main(
    const float* __restrict__ ploc, const float* __restrict__ pclf,
    const float* __restrict__ tloc, const int* __restrict__ tcls)
{
    __shared__ float    s_row[256 * NC];     // 21504 B
    __shared__ unsigned s_c[NB1];            // 8 KB (direct index, no CAS)
    __shared__ float    s_s[NB1];            // 8 KB
    __shared__ float    s_posce, s_loc;
    __shared__ unsigned s_np;

    int tid = threadIdx.x;
#pragma unroll
    for (int i = 0; i < NB1 / 256; i++) { s_c[i * 256 + tid] = 0u; s_s[i * 256 + tid] = 0.f; }
    if (tid == 0) { s_posce = 0.f; s_loc = 0.f; s_np = 0u; }

    // coalesced float4 stage: 256*21 floats = 1344 float4 (block base 21504B-aligned)
    {
        const float4* src = reinterpret_cast<const float4*>(pclf + (size_t)blockIdx.x * (256 * NC));
        float4* dst = reinterpret_cast<float4*>(s_row);
#pragma unroll
        for (int i = 0; i < 6; i++) {
            int j = i * 256 + tid;
            if (j < 1344) dst[j] = src[j];
        }
    }
    __syncthreads();

    int idx = blockIdx.x * 256 + tid;        // BA % 256 == 0, always valid
    int tc = tcls[idx];
    const float* row = s_row + tid * NC;     // 21 coprime 32 -> conflict-free
    float m = -1e30f, xt = 0.f;
    float v[NC];
#pragma unroll
    for (int c = 0; c < NC; c++) {
        float val = row[c];
        v[c] = val;
        m = fmaxf(m, val);
        xt = (c == tc) ? val : xt;
    }
    float s = 0.f;
#pragma unroll
    for (int c = 0; c < NC; c++) s += __expf(v[c] - m);
    float ce = __logf(s) + m - xt;

    if (tc != 0) {
        atomicAdd(&s_posce, ce);
        atomicAdd(&s_np, 1u);
        float4 p = *reinterpret_cast<const float4*>(ploc + (size_t)idx * 4);
        float4 t = *reinterpret_cast<const float4*>(tloc + (size_t)idx * 4);
        atomicAdd(&s_loc, fabsf(p.x - t.x) + fabsf(p.y - t.y) +
                          fabsf(p.z - t.z) + fabsf(p.w - t.w));
        g_ce[idx] = -1.0f;                   // sentinel: bits>>21 = 1532, never == t1
    } else {
        ce = fmaxf(ce, 0.f);
        g_ce[idx] = ce;
        unsigned b = __float_as_uint(ce) >> 21;
        atomicAdd(&s_c[b], 1u);
        atomicAdd(&s_s[b], ce);
    }
    __syncthreads();

    // flush (~50 occupied bins per block)
#pragma unroll
    for (int i = 0; i < NB1 / 256; i++) {
        int j = i * 256 + tid;
        unsigned c = s_c[j];
        if (c) { atomicAdd(&g_h1c[j], c); atomicAdd(&g_h1s[j], s_s[j]); }
    }
    if (tid == 0) {
        if (s_np) atomicAdd(&g_np, s_np);
        atomicAdd(&g_posce, s_posce);
        atomicAdd(&g_locsum, s_loc);
    }
}

// ---------------------------------------------------------------------------
// Selection (runs ONCE): coarse threshold bin t1, rank r within it, exact
// sum of all bins strictly above. 1 block x 256 threads.
__global__ void __launch_bounds__(256) k_sel() {
    __shared__ unsigned s_sf[256];
    __shared__ float    s_red[256];
    __shared__ int      s_bin;
    __shared__ unsigned s_r;

    int tid = threadIdx.x;
    unsigned np = g_np;
    unsigned nn = (unsigned)BA - np;
    unsigned k = (np == 0u) ? 0u : min(3u * np, nn);
    if (tid == 0) g_k = k;
    if (k == 0u) {
        if (tid == 0) { g_t1 = -1; g_r = 0u; g_above = 0.f; }
        return;
    }

    const int per = NB1 / 256;   // 8
    int base = tid * per;
    unsigned cl[per];
    unsigned local = 0u;
#pragma unroll
    for (int i = 0; i < per; i++) { cl[i] = g_h1c[base + i]; local += cl[i]; }
    s_sf[tid] = local;
    __syncthreads();
    for (int off = 1; off < 256; off <<= 1) {        // inclusive suffix scan
        unsigned vv = (tid + off < 256) ? s_sf[tid + off] : 0u;
        __syncthreads();
        s_sf[tid] += vv;
        __syncthreads();
    }
    unsigned running = (tid < 255) ? s_sf[tid + 1] : 0u;  // count strictly above my chunk
    for (int i = per - 1; i >= 0; i--) {
        unsigned c = cl[i];
        if (c > 0u && running < k && running + c >= k) { s_bin = base + i; s_r = k - running; }
        running += c;
    }
    __syncthreads();
    int t1 = s_bin;

    float ls = 0.f;
#pragma unroll
    for (int i = 0; i < per; i++) {
        int b = base + i;
        if (b > t1) ls += g_h1s[b];
    }
    s_red[tid] = ls;
    __syncthreads();
    for (int off = 128; off >= 1; off >>= 1) {
        if (tid < off) s_red[tid] += s_red[tid + off];
        __syncthreads();
    }
    if (tid == 0) { g_t1 = t1; g_r = s_r; g_above = s_red[0]; }
}

// ---------------------------------------------------------------------------
// Refine pass: float4 rescan of g_ce (L2-resident), sub-histogram of the
// boundary coarse bin only. 1092 blocks x 256 threads, 1 float4 each.
__global__ void __launch_bounds__(256) k_ref() {
    __shared__ unsigned s_c[SUB];
    __shared__ float    s_s[SUB];
    int tid = threadIdx.x;
    int t1 = g_t1;
    if (t1 < 0) return;
    s_c[tid] = 0u; s_s[tid] = 0.f;
    __syncthreads();

    int j = blockIdx.x * 256 + tid;
    if (j < NF4) {
        float4 v = reinterpret_cast<const float4*>(g_ce)[j];
        unsigned b;
        b = __float_as_uint(v.x); if ((int)(b >> 21) == t1) { atomicAdd(&s_c[(b >> 13) & 0xFFu], 1u); atomicAdd(&s_s[(b >> 13) & 0xFFu], v.x); }
        b = __float_as_uint(v.y); if ((int)(b >> 21) == t1) { atomicAdd(&s_c[(b >> 13) & 0xFFu], 1u); atomicAdd(&s_s[(b >> 13) & 0xFFu], v.y); }
        b = __float_as_uint(v.z); if ((int)(b >> 21) == t1) { atomicAdd(&s_c[(b >> 13) & 0xFFu], 1u); atomicAdd(&s_s[(b >> 13) & 0xFFu], v.z); }
        b = __float_as_uint(v.w); if ((int)(b >> 21) == t1) { atomicAdd(&s_c[(b >> 13) & 0xFFu], 1u); atomicAdd(&s_s[(b >> 13) & 0xFFu], v.w); }
    }
    __syncthreads();
    unsigned c = s_c[tid];
    if (c) { atomicAdd(&g_rc[tid], c); atomicAdd(&g_rs[tid], s_s[tid]); }
}

// ---------------------------------------------------------------------------
// Final: walk 256 sub-bins of boundary bin, bin-mean the last partial bin.
__global__ void k_final(float* __restrict__ out) {
    __shared__ unsigned s_fc[SUB];
    __shared__ float    s_fs[SUB];
    int tid = threadIdx.x;   // 32 threads
#pragma unroll
    for (int i = tid; i < SUB; i += 32) { s_fc[i] = g_rc[i]; s_fs[i] = g_rs[i]; }
    __syncwarp();
    if (tid == 0) {
        unsigned np = g_np, k = g_k, r = g_r;
        float top = 0.f;
        if (k > 0u) {
            float acc = g_above;
            unsigned run = 0u;
            for (int i = SUB - 1; i >= 0; i--) {
                unsigned c = s_fc[i];
                if (c) {
                    if (run + c >= r) {
                        acc += (float)(r - run) * (s_fs[i] / (float)c);  // 2^-10 rel bin width
                        break;
                    }
                    acc += s_fs[i];
                    run += c;
                }
            }
            top = acc;
        }
        out[0] = (g_posce + top) / ((float)np + (float)k);   // loss_cls
        out[1] = g_locsum / (float)np;                       // loss_loc
    }
}

// ---------------------------------------------------------------------------
extern "C" void kernel_launch(void* const* d_in, const int* in_sizes, int n_in,
                              void* d_out, int out_size)
{
    const float* ploc = (const float*)d_in[0];
    const float* pclf = (const float*)d_in[1];
    const float* tloc = (const float*)d_in[2];
    const int*   tcls = (const int*)d_in[3];
    float* out = (float*)d_out;

    k_init<<<2, 1024>>>();
    k_main<<<NBLK_MAIN, 256>>>(ploc, pclf, tloc, tcls);
    k_sel<<<1, 256>>>();
    k_ref<<<NBLK_REF, 256>>>();
    k_final<<<1, 32>>>(out);
}

// round 7
// speedup vs baseline: 2.3142x; 1.2352x over previous
#include <cuda_runtime.h>
#include <cstdint>

#define BA (128 * 8732)     // 1117696; == 512 * 2183 exactly
#define NC 21
#define NBLK_MAIN 2183      // 512 anchors per block, 2 chunks of 256
#define NB1 2048            // coarse bins: bits >> 21 (valid CE bins <= 1020)
#define SUB 256             // sub-bins in boundary bin: (bits >> 13) & 0xFF
#define NF4 (BA / 4)        // 279424 float4
#define NBLK_REF 296        // 296*256 threads * 4 f4 = 303104 >= NF4

// ---- scratch (no cudaMalloc allowed) ----
__device__ float    g_ce[BA];
__device__ unsigned g_h1c[NB1];
__device__ unsigned g_rc[SUB];
__device__ float    g_rs[SUB];
__device__ unsigned g_np;
__device__ float    g_posce, g_locsum, g_above;
__device__ int      g_t1;
__device__ unsigned g_r, g_k;

// ---------------------------------------------------------------------------
__global__ void k_init() {
    int tid = blockIdx.x * 1024 + threadIdx.x;   // 2 x 1024
    g_h1c[tid] = 0u;
    if (tid < SUB) { g_rc[tid] = 0u; g_rs[tid] = 0.f; }
    if (tid == 0) { g_np = 0u; g_posce = 0.f; g_locsum = 0.f; g_above = 0.f; }
}

// ---------------------------------------------------------------------------
// Main pass: 512 anchors/block in 2 staged chunks; counts-only smem histogram.
__global__ void __launch_bounds__(256) k_main(
    const float* __restrict__ ploc, const float* __restrict__ pclf,
    const float* __restrict__ tloc, const int* __restrict__ tcls)
{
    __shared__ float    s_row[256 * NC];     // 21504 B
    __shared__ unsigned s_c[NB1];            // 8 KB counts only
    __shared__ float    s_posce, s_loc;
    __shared__ unsigned s_np;

    int tid = threadIdx.x;
#pragma unroll
    for (int i = 0; i < NB1 / 256; i++) s_c[i * 256 + tid] = 0u;
    if (tid == 0) { s_posce = 0.f; s_loc = 0.f; s_np = 0u; }
    __syncthreads();

#pragma unroll 1
    for (int it = 0; it < 2; it++) {
        int chunk = blockIdx.x * 512 + it * 256;
        {   // coalesced float4 stage: 256*21 floats = 1344 float4
            const float4* src = reinterpret_cast<const float4*>(pclf + (size_t)chunk * NC);
            float4* dst = reinterpret_cast<float4*>(s_row);
#pragma unroll
            for (int i = 0; i < 6; i++) {
                int j = i * 256 + tid;
                if (j < 1344) dst[j] = src[j];
            }
        }
        __syncthreads();

        int idx = chunk + tid;
        int tc = tcls[idx];
        const float* row = s_row + tid * NC;         // 21 coprime 32: conflict-free
        float m = -1e30f, xt = 0.f;
        float v[NC];
#pragma unroll
        for (int c = 0; c < NC; c++) {
            float val = row[c];
            v[c] = val;
            m = fmaxf(m, val);
            xt = (c == tc) ? val : xt;
        }
        float s = 0.f;
#pragma unroll
        for (int c = 0; c < NC; c++) s += __expf(v[c] - m);
        float ce = __logf(s) + m - xt;

        if (tc != 0) {
            atomicAdd(&s_posce, ce);
            atomicAdd(&s_np, 1u);
            float4 p = *reinterpret_cast<const float4*>(ploc + (size_t)idx * 4);
            float4 t = *reinterpret_cast<const float4*>(tloc + (size_t)idx * 4);
            atomicAdd(&s_loc, fabsf(p.x - t.x) + fabsf(p.y - t.y) +
                              fabsf(p.z - t.z) + fabsf(p.w - t.w));
            g_ce[idx] = -1.0f;               // sentinel: bin 1532 > 1020, excluded later
        } else {
            ce = fmaxf(ce, 0.f);
            g_ce[idx] = ce;
            atomicAdd(&s_c[__float_as_uint(ce) >> 21], 1u);
        }
        __syncthreads();                     // protect s_row for next chunk
    }

    // flush (~60 occupied bins)
#pragma unroll
    for (int i = 0; i < NB1 / 256; i++) {
        int j = i * 256 + tid;
        unsigned c = s_c[j];
        if (c) atomicAdd(&g_h1c[j], c);
    }
    if (tid == 0) {
        if (s_np) atomicAdd(&g_np, s_np);
        atomicAdd(&g_posce, s_posce);
        atomicAdd(&g_locsum, s_loc);
    }
}

// ---------------------------------------------------------------------------
// Selection (once): coarse threshold bin t1 and in-bin rank r. 1 x 256.
__global__ void __launch_bounds__(256) k_sel() {
    __shared__ unsigned s_sf[256];
    __shared__ int      s_bin;
    __shared__ unsigned s_r;

    int tid = threadIdx.x;
    unsigned np = g_np;
    unsigned nn = (unsigned)BA - np;
    unsigned k = (np == 0u) ? 0u : min(3u * np, nn);
    if (tid == 0) g_k = k;
    if (k == 0u) {
        if (tid == 0) { g_t1 = -1; g_r = 0u; }
        return;
    }

    const int per = NB1 / 256;   // 8
    int base = tid * per;
    unsigned cl[per];
    unsigned local = 0u;
#pragma unroll
    for (int i = 0; i < per; i++) { cl[i] = g_h1c[base + i]; local += cl[i]; }
    s_sf[tid] = local;
    __syncthreads();
    for (int off = 1; off < 256; off <<= 1) {        // inclusive suffix scan
        unsigned vv = (tid + off < 256) ? s_sf[tid + off] : 0u;
        __syncthreads();
        s_sf[tid] += vv;
        __syncthreads();
    }
    unsigned running = (tid < 255) ? s_sf[tid + 1] : 0u;
    for (int i = per - 1; i >= 0; i--) {
        unsigned c = cl[i];
        if (c > 0u && running < k && running + c >= k) { s_bin = base + i; s_r = k - running; }
        running += c;
    }
    __syncthreads();
    if (tid == 0) { g_t1 = s_bin; g_r = s_r; }
}

// ---------------------------------------------------------------------------
// Refine: grid-strided float4 rescan. Accumulates (a) exact sum of CE with
// bin in (t1, 1020], (b) sub-histogram of bin == t1. 296 x 256, 4 f4/thread.
__global__ void __launch_bounds__(256) k_ref() {
    __shared__ unsigned s_c[SUB];
    __shared__ float    s_s[SUB];
    __shared__ float    s_red[256];
    int tid = threadIdx.x;
    int t1 = g_t1;
    if (t1 < 0) return;
    s_c[tid] = 0u; s_s[tid] = 0.f;
    __syncthreads();

    unsigned ut1 = (unsigned)t1;
    float above = 0.f;
    const float4* ce4 = reinterpret_cast<const float4*>(g_ce);
#pragma unroll
    for (int it = 0; it < 4; it++) {
        int j = (it * NBLK_REF + blockIdx.x) * 256 + tid;
        if (j < NF4) {
            float4 v = ce4[j];
            unsigned b, e;
            b = __float_as_uint(v.x); e = b >> 21;
            if (e > ut1) { if (e <= 1020u) above += v.x; }
            else if (e == ut1) { unsigned sb = (b >> 13) & 0xFFu; atomicAdd(&s_c[sb], 1u); atomicAdd(&s_s[sb], v.x); }
            b = __float_as_uint(v.y); e = b >> 21;
            if (e > ut1) { if (e <= 1020u) above += v.y; }
            else if (e == ut1) { unsigned sb = (b >> 13) & 0xFFu; atomicAdd(&s_c[sb], 1u); atomicAdd(&s_s[sb], v.y); }
            b = __float_as_uint(v.z); e = b >> 21;
            if (e > ut1) { if (e <= 1020u) above += v.z; }
            else if (e == ut1) { unsigned sb = (b >> 13) & 0xFFu; atomicAdd(&s_c[sb], 1u); atomicAdd(&s_s[sb], v.z); }
            b = __float_as_uint(v.w); e = b >> 21;
            if (e > ut1) { if (e <= 1020u) above += v.w; }
            else if (e == ut1) { unsigned sb = (b >> 13) & 0xFFu; atomicAdd(&s_c[sb], 1u); atomicAdd(&s_s[sb], v.w); }
        }
    }
    // block-reduce 'above'
    s_red[tid] = above;
    __syncthreads();
#pragma unroll
    for (int off = 128; off >= 1; off >>= 1) {
        if (tid < off) s_red[tid] += s_red[tid + off];
        __syncthreads();
    }
    if (tid == 0 && s_red[0] != 0.f) atomicAdd(&g_above, s_red[0]);
    unsigned c = s_c[tid];
    if (c) { atomicAdd(&g_rc[tid], c); atomicAdd(&g_rs[tid], s_s[tid]); }
}

// ---------------------------------------------------------------------------
// Final: walk 256 sub-bins of boundary bin, bin-mean the partial bin.
__global__ void k_final(float* __restrict__ out) {
    __shared__ unsigned s_fc[SUB];
    __shared__ float    s_fs[SUB];
    int tid = threadIdx.x;   // 32
#pragma unroll
    for (int i = tid; i < SUB; i += 32) { s_fc[i] = g_rc[i]; s_fs[i] = g_rs[i]; }
    __syncwarp();
    if (tid == 0) {
        unsigned np = g_np, k = g_k, r = g_r;
        float top = 0.f;
        if (k > 0u) {
            float acc = g_above;
            unsigned run = 0u;
            for (int i = SUB - 1; i >= 0; i--) {
                unsigned c = s_fc[i];
                if (c) {
                    if (run + c >= r) {
                        acc += (float)(r - run) * (s_fs[i] / (float)c);  // 2^-10 rel width
                        break;
                    }
                    acc += s_fs[i];
                    run += c;
                }
            }
            top = acc;
        }
        out[0] = (g_posce + top) / ((float)np + (float)k);   // loss_cls
        out[1] = g_locsum / (float)np;                       // loss_loc
    }
}

// ---------------------------------------------------------------------------
extern "C" void kernel_launch(void* const* d_in, const int* in_sizes, int n_in,
                              void* d_out, int out_size)
{
    const float* ploc = (const float*)d_in[0];
    const float* pclf = (const float*)d_in[1];
    const float* tloc = (const float*)d_in[2];
    const int*   tcls = (const int*)d_in[3];
    float* out = (float*)d_out;

    k_init<<<2, 1024>>>();
    k_main<<<NBLK_MAIN, 256>>>(ploc, pclf, tloc, tcls);
    k_sel<<<1, 256>>>();
    k_ref<<<NBLK_REF, 256>>>();
    k_final<<<1, 32>>>(out);
}